// round 1
// baseline (speedup 1.0000x reference)
#include <cuda_runtime.h>

// Reference semantics after dead-code elimination:
//   r  = eye(3)                       (unconditional overwrite in reference)
//   tb = -mean(mkpts0, axis=1)        ( = -r @ src_mean with r = I )
// Output: 12 floats = [r row-major (9), tb (3)].
//
// Inputs (metadata order): mkpts0 [3,8192] f32, mkpts1 [3,8192] f32,
// valid_scores [8192,8192] f32 (unused).

#define ROWLEN 8192
#define TPB 256

__global__ void svdhead_kernel(const float* __restrict__ mkpts0,
                               float* __restrict__ out, int n) {
    // grid.x = 3 : block b computes -mean(mkpts0[b, :])
    const int b = blockIdx.x;
    const int t = threadIdx.x;

    // Block 0 also writes the identity matrix (indices 0..8).
    if (b == 0 && t < 9) {
        out[t] = ((t & 3) == 0) ? 1.0f : 0.0f;  // t = 0,4,8 -> 1
    }

    const float* row = mkpts0 + (size_t)b * n;
    float sum = 0.0f;
    // 8192 / 256 = 32 elements per thread; vectorize with float4.
    const float4* row4 = reinterpret_cast<const float4*>(row);
    const int n4 = n >> 2;  // 2048
    for (int i = t; i < n4; i += TPB) {
        float4 v = row4[i];
        sum += (v.x + v.y) + (v.z + v.w);
    }

    // Warp reduction
    #pragma unroll
    for (int off = 16; off > 0; off >>= 1)
        sum += __shfl_xor_sync(0xFFFFFFFFu, sum, off);

    // Cross-warp reduction via shared memory
    __shared__ float warp_sums[TPB / 32];
    if ((t & 31) == 0) warp_sums[t >> 5] = sum;
    __syncthreads();

    if (t < (TPB / 32)) {
        float s = warp_sums[t];
        #pragma unroll
        for (int off = (TPB / 64); off > 0; off >>= 1)
            s += __shfl_xor_sync(0xFFFFFFFFu, s, off);
        if (t == 0)
            out[9 + b] = -s / (float)n;
    }
}

extern "C" void kernel_launch(void* const* d_in, const int* in_sizes, int n_in,
                              void* d_out, int out_size) {
    const float* mkpts0 = (const float*)d_in[0];
    float* out = (float*)d_out;
    const int n = in_sizes[0] / 3;  // 8192
    svdhead_kernel<<<3, TPB>>>(mkpts0, out, n);
}

// round 2
// speedup vs baseline: 1.4375x; 1.4375x over previous
#include <cuda_runtime.h>

// Reference semantics after dead-code elimination:
//   r  = eye(3)                       (unconditional overwrite in reference)
//   tb = -mean(mkpts0, axis=1)        ( = -r @ src_mean with r = I )
// Output: 12 floats = [r row-major (9), tb (3)].
//
// Inputs (metadata order): mkpts0 [3,8192] f32, mkpts1 [3,8192] f32 (unused),
// valid_scores [8192,8192] f32 (unused).

#define ROWLEN   8192
#define TPB      1024
#define NWARPS   (TPB / 32)
#define INV_NEG  (-1.0f / 8192.0f)   // exact: power-of-two divisor

__global__ void __launch_bounds__(TPB, 1)
svdhead_kernel(const float* __restrict__ mkpts0, float* __restrict__ out) {
    const int b = blockIdx.x;       // row 0..2
    const int t = threadIdx.x;

    // Block 0 writes the 3x3 identity (row-major, indices 0..8).
    if (b == 0 && t < 9) {
        out[t] = ((t & 3) == 0) ? 1.0f : 0.0f;   // t = 0,4,8 -> 1
    }

    // 8192 floats = 2048 float4; 1024 threads -> exactly 2 float4 each,
    // both issued back-to-back (one DRAM round trip, MLP=2 per thread,
    // 2048 loads in flight block-wide).
    const float4* row4 = reinterpret_cast<const float4*>(mkpts0) + (size_t)b * (ROWLEN / 4);
    float4 v0 = row4[t];
    float4 v1 = row4[t + TPB];

    float sum = ((v0.x + v0.y) + (v0.z + v0.w)) + ((v1.x + v1.y) + (v1.z + v1.w));

    // Warp tree reduce: 5 shfl.
    #pragma unroll
    for (int off = 16; off > 0; off >>= 1)
        sum += __shfl_xor_sync(0xFFFFFFFFu, sum, off);

    __shared__ float warp_sums[NWARPS];
    if ((t & 31) == 0) warp_sums[t >> 5] = sum;
    __syncthreads();

    // Single warp folds the 32 warp sums: 1 LDS + 5 shfl + 1 STG.
    if (t < 32) {
        float s = warp_sums[t];
        #pragma unroll
        for (int off = 16; off > 0; off >>= 1)
            s += __shfl_xor_sync(0xFFFFFFFFu, s, off);
        if (t == 0)
            out[9 + b] = s * INV_NEG;
    }
}

extern "C" void kernel_launch(void* const* d_in, const int* in_sizes, int n_in,
                              void* d_out, int out_size) {
    const float* mkpts0 = (const float*)d_in[0];
    float* out = (float*)d_out;
    svdhead_kernel<<<3, TPB>>>(mkpts0, out);
}

// round 3
// speedup vs baseline: 1.4577x; 1.0141x over previous
#include <cuda_runtime.h>

// Reference semantics after dead-code elimination:
//   r  = eye(3)                       (unconditional overwrite in reference)
//   tb = -mean(mkpts0, axis=1)        ( = -r @ src_mean with r = I )
// Output: 12 floats = [r row-major (9), tb (3)].
//
// Inputs (metadata order): mkpts0 [3,8192] f32, mkpts1 [3,8192] f32 (unused),
// valid_scores [8192,8192] f32 (unused).

#define ROWLEN   8192
#define TPB      256
#define NWARPS   (TPB / 32)          // 8
#define LD       (ROWLEN / 4 / TPB)  // 8 float4 per thread
#define INV_NEG  (-1.0f / 8192.0f)   // exact: power-of-two divisor

__global__ void __launch_bounds__(TPB, 1)
svdhead_kernel(const float* __restrict__ mkpts0, float* __restrict__ out) {
    const int b = blockIdx.x;       // row 0..2
    const int t = threadIdx.x;

    // Block 0 writes the 3x3 identity (row-major, indices 0..8).
    if (b == 0 && t < 9) {
        out[t] = ((t & 3) == 0) ? 1.0f : 0.0f;   // t = 0,4,8 -> 1
    }

    // 2048 float4 per row; 256 threads x 8 fully-unrolled LDG.128 each.
    // All 8 loads issued back-to-back -> one DRAM round trip (MLP=8/thread).
    const float4* row4 = reinterpret_cast<const float4*>(mkpts0)
                       + (size_t)b * (ROWLEN / 4) + t;
    float4 v[LD];
    #pragma unroll
    for (int i = 0; i < LD; i++) v[i] = v[i] = row4[i * TPB];

    // Pairwise FADD tree over the 32 scalars (depth 5, ~20 cyc).
    float p[LD];
    #pragma unroll
    for (int i = 0; i < LD; i++) p[i] = (v[i].x + v[i].y) + (v[i].z + v[i].w);
    float sum = ((p[0] + p[1]) + (p[2] + p[3])) + ((p[4] + p[5]) + (p[6] + p[7]));

    // Warp tree reduce: 5 shfl.
    #pragma unroll
    for (int off = 16; off > 0; off >>= 1)
        sum += __shfl_xor_sync(0xFFFFFFFFu, sum, off);

    __shared__ float warp_sums[NWARPS];
    if ((t & 31) == 0) warp_sums[t >> 5] = sum;
    __syncthreads();

    // First warp folds the 8 warp sums: 1 LDS + 3 shfl + 1 STG.
    if (t < NWARPS) {
        float s = warp_sums[t];
        #pragma unroll
        for (int off = NWARPS / 2; off > 0; off >>= 1)
            s += __shfl_xor_sync(0x000000FFu, s, off);
        if (t == 0)
            out[9 + b] = s * INV_NEG;
    }
}

extern "C" void kernel_launch(void* const* d_in, const int* in_sizes, int n_in,
                              void* d_out, int out_size) {
    const float* mkpts0 = (const float*)d_in[0];
    float* out = (float*)d_out;
    svdhead_kernel<<<3, TPB>>>(mkpts0, out);
}